// round 16
// baseline (speedup 1.0000x reference)
#include <cuda_runtime.h>
#include <cuda_fp16.h>
#include <cstdint>

// lstm_model_8873402433789 R16 — thin-warp fp16 mma.sync LSTM, amortized.
// Warp w: units 8w..8w+7 (permuted gate rows, 2 m-tiles) x 16 batch rows
// (2 n-tiles) = 12 MMAs/step. t-loop unrolled x2 with per-parity precomputed
// addresses (kills R15's 30% ALU overhead). 512 CTAs x 128 thr.

#define TT 200
#define DD 60
#define CROWS 16
#define WSTR 56    // weight row stride (halfs), 112B
#define HSTR 40    // h row stride (halfs), 80B; layout [buf][16 rows][HSTR]
#define XSTR 40    // x row stride; cols 0-15 buf0, 16-31 buf1

static __device__ __forceinline__ uint32_t s2u(const void* p) {
    uint32_t a;
    asm("{ .reg .u64 t; cvta.to.shared.u64 t, %1; cvt.u32.u64 %0, t; }"
        : "=r"(a) : "l"(p));
    return a;
}
static __device__ __forceinline__ uint32_t hpack(float lo, float hi) {
    __half2 t = __floats2half2_rn(lo, hi);
    return *(uint32_t*)&t;
}
static __device__ __forceinline__ __half2 tanh2(uint32_t g2) {
    uint32_t r;
    asm("tanh.approx.f16x2 %0, %1;" : "=r"(r) : "r"(g2));
    return *(__half2*)&r;
}
static __device__ __forceinline__ void ldsm4(uint32_t* r, uint32_t addr) {
    asm volatile("ldmatrix.sync.aligned.m8n8.x4.shared.b16 {%0,%1,%2,%3}, [%4];"
                 : "=r"(r[0]), "=r"(r[1]), "=r"(r[2]), "=r"(r[3]) : "r"(addr));
}
static __device__ __forceinline__ void ldsm2(uint32_t* r, uint32_t addr) {
    asm volatile("ldmatrix.sync.aligned.m8n8.x2.shared.b16 {%0,%1}, [%2];"
                 : "=r"(r[0]), "=r"(r[1]) : "r"(addr));
}
static __device__ __forceinline__ void mma16816(float* d, const uint32_t* a,
                                                const uint32_t* b) {
    asm volatile(
        "mma.sync.aligned.m16n8k16.row.col.f32.f16.f16.f32 "
        "{%0,%1,%2,%3}, {%4,%5,%6,%7}, {%8,%9}, {%0,%1,%2,%3};"
        : "+f"(d[0]), "+f"(d[1]), "+f"(d[2]), "+f"(d[3])
        : "r"(a[0]), "r"(a[1]), "r"(a[2]), "r"(a[3]), "r"(b[0]), "r"(b[1]));
}

__global__ void __launch_bounds__(128, 5) lstm_thin2_kernel(
    const float* __restrict__ x,  const float* __restrict__ W,
    const float* __restrict__ U,  const float* __restrict__ b,
    const float* __restrict__ W1, const float* __restrict__ b1,
    const float* __restrict__ W2, const float* __restrict__ b2,
    float* __restrict__ out)
{
    __shared__ __align__(16) __half wsm[128 * WSTR];       // permuted weights
    __shared__ __align__(16) __half hsm[2 * CROWS * HSTR]; // h, dbl buffered
    __shared__ __align__(16) __half xsm[CROWS * XSTR];     // x, dbl buf in-row

    const int tid = threadIdx.x;
    const int l   = tid & 31;
    const int w   = tid >> 5;        // warp: units 8w..8w+7
    const int gid = l >> 2, tig = l & 3;
    const int lr8 = l & 7;

    // ---- weights, gate rows permuted; 0.5 folded into i/f/o; K=[U 0-31|W 32-47]
    // perm: gate(type t, unit u) -> 32*(u>>3) + 16*(t>>1) + 8*(t&1) + (u&7)
    for (int idx = tid; idx < 128 * 48; idx += 128) {
        int g = idx / 48, k = idx - g * 48;
        int typ = g >> 5, u = g & 31;
        int row = 32 * (u >> 3) + 16 * (typ >> 1) + 8 * (typ & 1) + (u & 7);
        float src = (k < 32) ? U[k * 128 + g] : W[(k - 32) * 128 + g];
        float sc  = (typ == 2) ? 1.0f : 0.5f;
        wsm[row * WSTR + k] = __float2half_rn(src * sc);
    }
    __syncthreads();

    // ---- A fragments: afr[mtl 0=(i|f),1=(c|o)][ks 0,1=U; 2=W]
    const uint32_t wsmu = s2u(wsm);
    uint32_t afr[2][3][4];
    {
        int laneRow = lr8 + 8 * ((l >> 3) & 1);
        int laneK   = 8 * (l >> 4);
#pragma unroll
        for (int mtl = 0; mtl < 2; ++mtl)
#pragma unroll
            for (int ks = 0; ks < 3; ++ks)
                ldsm4(afr[mtl][ks],
                      wsmu + ((32 * w + 16 * mtl + laneRow) * WSTR + 16 * ks + laneK) * 2);
    }
    const int unit = 8 * w + gid;
    const float bi = 0.5f * b[unit], bf = 0.5f * b[32 + unit];
    const float bc = b[64 + unit],   bo = 0.5f * b[96 + unit];

    // ---- zero h buf0; stage x(0) (float2/thread); prefetch x(1)
    for (int idx = tid; idx < CROWS * HSTR; idx += 128)
        hsm[idx] = __float2half_rn(0.0f);
    const int xrow = tid >> 3, xfp = tid & 7;   // 16 rows x 8 feat-pairs
    const float2* xg = (const float2*)(x +
        ((size_t)blockIdx.x * CROWS + xrow) * (TT * 16) + 2 * xfp);
    *(uint32_t*)(xsm + xrow * XSTR + 2 * xfp) = hpack(xg[0].x, xg[0].y);
    float2 pf = xg[8];     // x(1)
    __syncthreads();

    // ---- precomputed addresses (both parities)
    const uint32_t hbu = s2u(hsm), xbu = s2u(xsm);
    uint32_t hld[2][2], xld[2][2];          // [parity][nt] ldsm sources
#pragma unroll
    for (int p2 = 0; p2 < 2; ++p2)
#pragma unroll
        for (int nt = 0; nt < 2; ++nt) {
            hld[p2][nt] = hbu + (p2 * (CROWS * HSTR) + (8 * nt + lr8) * HSTR + 8 * (l >> 3)) * 2;
            xld[p2][nt] = xbu + ((8 * nt + lr8) * XSTR + p2 * 16 + 8 * ((l >> 3) & 1)) * 2;
        }
    __half* hst[2];                          // [parity] h store base (row term added per q)
    hst[0] = hsm + unit;  hst[1] = hsm + CROWS * HSTR + unit;
    uint32_t* xst[2];
    xst[0] = (uint32_t*)(xsm + xrow * XSTR + 2 * xfp);
    xst[1] = (uint32_t*)(xsm + xrow * XSTR + 16 + 2 * xfp);

    uint32_t xf[2][2];                       // [nt] fragments, current step
    ldsm2(xf[0], xld[0][0]);
    ldsm2(xf[1], xld[0][1]);

    float cst[2][2] = {{0.0f, 0.0f}, {0.0f, 0.0f}};   // [nt][q]

#define STEP(P, PN, T)                                                        \
    {                                                                         \
        /* stage x(t+1) -> buf PN; prefetch x(t+2) */                         \
        *xst[PN] = hpack(pf.x, pf.y);                                         \
        int tn = (T) + 2; if (tn > TT - 1) tn = TT - 1;                       \
        pf = xg[tn * 8];                                                      \
        /* x-MMAs with xf(t) */                                               \
        float dac[2][2][4];                                                   \
        _Pragma("unroll")                                                     \
        for (int nt = 0; nt < 2; ++nt) {                                      \
            dac[0][nt][0] = bi; dac[0][nt][1] = bi;                           \
            dac[0][nt][2] = bf; dac[0][nt][3] = bf;                           \
            dac[1][nt][0] = bc; dac[1][nt][1] = bc;                           \
            dac[1][nt][2] = bo; dac[1][nt][3] = bo;                           \
            mma16816(dac[0][nt], afr[0][2], xf[nt]);                          \
            mma16816(dac[1][nt], afr[1][2], xf[nt]);                          \
        }                                                                     \
        __syncthreads();   /* h(t) + x(t+1) visible */                        \
        _Pragma("unroll")                                                     \
        for (int nt = 0; nt < 2; ++nt) {                                      \
            uint32_t bh[4];                                                   \
            ldsm4(bh, hld[P][nt]);                                            \
            ldsm2(xf[nt], xld[PN][nt]);     /* xf(t+1) for next step */       \
            mma16816(dac[0][nt], afr[0][0], &bh[0]);                          \
            mma16816(dac[0][nt], afr[0][1], &bh[2]);                          \
            mma16816(dac[1][nt], afr[1][0], &bh[0]);                          \
            mma16816(dac[1][nt], afr[1][1], &bh[2]);                          \
        }                                                                     \
        _Pragma("unroll")                                                     \
        for (int nt = 0; nt < 2; ++nt) {                                      \
            __half2 ti = tanh2(hpack(dac[0][nt][0], dac[0][nt][1]));          \
            __half2 tf = tanh2(hpack(dac[0][nt][2], dac[0][nt][3]));          \
            __half2 to = tanh2(hpack(dac[1][nt][2], dac[1][nt][3]));          \
            _Pragma("unroll")                                                 \
            for (int q = 0; q < 2; ++q) {                                     \
                float tiq = q ? __high2float(ti) : __low2float(ti);           \
                float tfq = q ? __high2float(tf) : __low2float(tf);           \
                float toq = q ? __high2float(to) : __low2float(to);           \
                float cc  = fmaxf(dac[1][nt][q], 0.0f);                       \
                float co  = cst[nt][q];                                       \
                float c   = 0.5f * (fmaf(tfq, co, co) + fmaf(tiq, cc, cc));   \
                cst[nt][q] = c;                                               \
                float hv  = fmaf(0.5f, toq, 0.5f) * fmaxf(c, 0.0f);           \
                hst[PN][(8 * nt + 2 * tig + q) * HSTR] = __float2half_rn(hv); \
            }                                                                 \
        }                                                                     \
    }

#pragma unroll 1
    for (int t = 0; t < TT; t += 2) {
        STEP(0, 1, t)
        STEP(1, 0, t + 1)
    }
#undef STEP

    // ---- output heads: final h in buf0 (t=200 even)
    __syncthreads();
    for (int idx = tid; idx < CROWS * DD; idx += 128) {
        int rr = idx / DD, d = idx - rr * DD;
        const __half* hr = hsm + rr * HSTR;
        float aL = b1[d], aA = b2[d];
#pragma unroll
        for (int u = 0; u < 32; ++u) {
            float hu = __half2float(hr[u]);
            aL = fmaf(hu, W1[u * DD + d], aL);
            aA = fmaf(hu, W2[u * DD + d], aA);
        }
        size_t grow = (size_t)blockIdx.x * CROWS + rr;
        out[grow * DD + d] = aL;
        out[(8192 + grow) * DD + d] = aA;
    }
}

extern "C" void kernel_launch(void* const* d_in, const int* in_sizes, int n_in,
                              void* d_out, int out_size) {
    const float* x  = (const float*)d_in[0];
    const float* W  = (const float*)d_in[1];
    const float* U  = (const float*)d_in[2];
    const float* b  = (const float*)d_in[3];
    const float* W1 = (const float*)d_in[4];
    const float* b1 = (const float*)d_in[5];
    const float* W2 = (const float*)d_in[6];
    const float* b2 = (const float*)d_in[7];
    float* out = (float*)d_out;

    // 8192 rows / 16 per CTA = 512 CTAs x 128 thr (4 thin warps, 2 n-tiles)
    lstm_thin2_kernel<<<512, 128>>>(x, W, U, b, W1, b1, W2, b2, out);
}

// round 17
// speedup vs baseline: 1.1252x; 1.1252x over previous
#include <cuda_runtime.h>
#include <cuda_fp16.h>
#include <cstdint>

// lstm_model_8873402433789 R17 — R12 geometry + f16x2 tanh sigmoid +
// parity-unrolled precomputed addresses + 64-wide pair barrier.
// 512 CTAs x 128 thr; warp (mg,ng) = 16 units x 8 rows; 12 MMAs/warp-step.

#define TT 200
#define CROWS 16
#define DD 60
#define WSTR 56    // weight row stride (halfs), 112B
#define HSTR 72    // h row stride: buf0 cols 0-31, buf1 32-63, pad
#define XSTR 40    // x row stride: buf0 cols 0-15, buf1 16-31

static __device__ __forceinline__ uint32_t s2u(const void* p) {
    uint32_t a;
    asm("{ .reg .u64 t; cvta.to.shared.u64 t, %1; cvt.u32.u64 %0, t; }"
        : "=r"(a) : "l"(p));
    return a;
}
static __device__ __forceinline__ uint32_t hpack(float lo, float hi) {
    __half2 t = __floats2half2_rn(lo, hi);
    return *(uint32_t*)&t;
}
static __device__ __forceinline__ __half2 tanh2(uint32_t g2) {
    uint32_t r;
    asm("tanh.approx.f16x2 %0, %1;" : "=r"(r) : "r"(g2));
    return *(__half2*)&r;
}
static __device__ __forceinline__ void ldsm4(uint32_t* r, uint32_t addr) {
    asm volatile("ldmatrix.sync.aligned.m8n8.x4.shared.b16 {%0,%1,%2,%3}, [%4];"
                 : "=r"(r[0]), "=r"(r[1]), "=r"(r[2]), "=r"(r[3]) : "r"(addr));
}
static __device__ __forceinline__ void ldsm2(uint32_t* r, uint32_t addr) {
    asm volatile("ldmatrix.sync.aligned.m8n8.x2.shared.b16 {%0,%1}, [%2];"
                 : "=r"(r[0]), "=r"(r[1]) : "r"(addr));
}
static __device__ __forceinline__ void mma16816(float* d, const uint32_t* a,
                                                const uint32_t* b) {
    asm volatile(
        "mma.sync.aligned.m16n8k16.row.col.f32.f16.f16.f32 "
        "{%0,%1,%2,%3}, {%4,%5,%6,%7}, {%8,%9}, {%0,%1,%2,%3};"
        : "+f"(d[0]), "+f"(d[1]), "+f"(d[2]), "+f"(d[3])
        : "r"(a[0]), "r"(a[1]), "r"(a[2]), "r"(a[3]), "r"(b[0]), "r"(b[1]));
}

__global__ void __launch_bounds__(128, 4) lstm_r17_kernel(
    const float* __restrict__ x,  const float* __restrict__ W,
    const float* __restrict__ U,  const float* __restrict__ b,
    const float* __restrict__ W1, const float* __restrict__ b1,
    const float* __restrict__ W2, const float* __restrict__ b2,
    float* __restrict__ out)
{
    __shared__ __align__(16) __half wsm[128 * WSTR];       // weights (init only)
    __shared__ __align__(16) __half hsm[CROWS * HSTR];     // h, dbl buf in-row
    __shared__ __align__(16) __half xpr[4 * 8 * XSTR];     // x, warp-private

    const int tid = threadIdx.x;
    const int l   = tid & 31;
    const int w   = tid >> 5;
    const int gid = l >> 2, tig = l & 3;
    const int mg  = w & 1;        // unit half
    const int ng  = w >> 1;       // pair id (8-row group)
    const int lr8 = l & 7;

    // ---- weights fp16, 0.5 folded into i/f/o (gate types 0,1,3): K=[U 0-31|W 32-47]
    for (int idx = tid; idx < 128 * 48; idx += 128) {
        int g = idx / 48, k = idx - g * 48;
        float src = (k < 32) ? U[k * 128 + g] : W[(k - 32) * 128 + g];
        float sc  = (g >= 64 && g < 96) ? 1.0f : 0.5f;   // c-gates unscaled
        wsm[g * WSTR + k] = __float2half_rn(src * sc);
    }
    __syncthreads();

    // ---- A fragments: afr[mt 0=i,1=f,2=c,3=o][ks 0,1=U; 2=W]
    const uint32_t wsmu = s2u(wsm);
    uint32_t afr[4][3][4];
    {
        int laneRow = lr8 + 8 * ((l >> 3) & 1);
        int laneK   = 8 * (l >> 4);
#pragma unroll
        for (int mt = 0; mt < 4; ++mt) {
            int Gmt = 32 * mt + 16 * mg;
#pragma unroll
            for (int ks = 0; ks < 3; ++ks)
                ldsm4(afr[mt][ks], wsmu + ((Gmt + laneRow) * WSTR + 16 * ks + laneK) * 2);
        }
    }
    float bv[4][2];
#pragma unroll
    for (int mt = 0; mt < 4; ++mt) {
        float sc = (mt == 2) ? 1.0f : 0.5f;
        bv[mt][0] = sc * b[32 * mt + 16 * mg + gid];
        bv[mt][1] = sc * b[32 * mt + 16 * mg + gid + 8];
    }

    // ---- init h buf0 = 0
    for (int idx = tid; idx < CROWS * 32; idx += 128) {
        int rr = idx >> 5, cc = idx & 31;
        hsm[rr * HSTR + cc] = __float2half_rn(0.0f);
    }
    // ---- stage x(0) privately, prefetch x(1)
    const int prow = l >> 2, pseg = l & 3;
    const float4* xg = (const float4*)(x +
        ((size_t)blockIdx.x * CROWS + 8 * ng + prow) * (TT * 16)) + pseg;
    __half* xmy = xpr + (w * 8 + prow) * XSTR;
    {
        float4 v = xg[0];
        *(uint2*)(xmy + pseg * 4) = make_uint2(hpack(v.x, v.y), hpack(v.z, v.w));
    }
    float4 pf = xg[4];
    __syncthreads();

    // ---- precomputed per-parity addresses
    const uint32_t hbu = s2u(hsm);
    const uint32_t xbu = s2u(xpr + w * 8 * XSTR);
    uint32_t hld[2], xld[2];
    uint32_t* xst[2];
    __half* hstp[2];
#pragma unroll
    for (int p2 = 0; p2 < 2; ++p2) {
        hld[p2] = hbu + ((8 * ng + lr8) * HSTR + p2 * 32 + 8 * (l >> 3)) * 2;
        xld[p2] = xbu + (lr8 * XSTR + p2 * 16 + 8 * ((l >> 3) & 1)) * 2;
        xst[p2] = (uint32_t*)(xmy + p2 * 16 + pseg * 4);
        hstp[p2] = hsm + (8 * ng + 2 * tig) * HSTR + p2 * 32 + 16 * mg + gid;
    }
    const int bar = 1 + ng;

    uint32_t xf[2];
    ldsm2(xf, xld[0]);           // x(0)

    float cst[2][2] = {{0.0f, 0.0f}, {0.0f, 0.0f}};   // [h][q]

#define STEP(P, PN, T)                                                         \
    {                                                                          \
        /* stage x(t+1) -> buf PN; prefetch x(t+2) */                          \
        *xst[PN] = hpack(pf.x, pf.y);                                          \
        *(xst[PN] + 1) = hpack(pf.z, pf.w);                                    \
        int tn = (T) + 2; if (tn > TT - 1) tn = TT - 1;                        \
        pf = xg[tn * 4];                                                       \
        /* x-MMAs with xf(t) */                                                \
        float dac[4][4];                                                       \
        _Pragma("unroll")                                                      \
        for (int mt = 0; mt < 4; ++mt) {                                       \
            dac[mt][0] = bv[mt][0]; dac[mt][1] = bv[mt][0];                    \
            dac[mt][2] = bv[mt][1]; dac[mt][3] = bv[mt][1];                    \
            mma16816(dac[mt], afr[mt][2], xf);                                 \
        }                                                                      \
        /* pair barrier: partner's h(t) visible; also orders own x STS/ldsm */ \
        asm volatile("bar.sync %0, %1;" :: "r"(bar), "r"(64) : "memory");      \
        uint32_t bh[4];                                                        \
        ldsm4(bh, hld[P]);                                                     \
        ldsm2(xf, xld[PN]);          /* xf(t+1) for next step */               \
        _Pragma("unroll")                                                      \
        for (int mt = 0; mt < 4; ++mt) {                                       \
            mma16816(dac[mt], afr[mt][0], &bh[0]);                             \
            mma16816(dac[mt], afr[mt][1], &bh[2]);                             \
        }                                                                      \
        /* update: tanh2 across batch-pairs, c fp32, store h(t+1) -> buf PN */ \
        _Pragma("unroll")                                                      \
        for (int h = 0; h < 2; ++h) {                                          \
            const int e0 = 2 * h;                                              \
            __half2 ti = tanh2(hpack(dac[0][e0], dac[0][e0 + 1]));             \
            __half2 tf = tanh2(hpack(dac[1][e0], dac[1][e0 + 1]));             \
            __half2 to = tanh2(hpack(dac[3][e0], dac[3][e0 + 1]));             \
            _Pragma("unroll")                                                  \
            for (int q = 0; q < 2; ++q) {                                      \
                float tiq = q ? __high2float(ti) : __low2float(ti);            \
                float tfq = q ? __high2float(tf) : __low2float(tf);            \
                float toq = q ? __high2float(to) : __low2float(to);            \
                float cc  = fmaxf(dac[2][e0 + q], 0.0f);                       \
                float co  = cst[h][q];                                         \
                float c   = 0.5f * (fmaf(tfq, co, co) + fmaf(tiq, cc, cc));    \
                cst[h][q] = c;                                                 \
                float hv  = fmaf(0.5f, toq, 0.5f) * fmaxf(c, 0.0f);            \
                hstp[PN][q * HSTR + 8 * h] = __float2half_rn(hv);              \
            }                                                                  \
        }                                                                      \
    }

#pragma unroll 1
    for (int t = 0; t < TT; t += 2) {
        STEP(0, 1, t)
        STEP(1, 0, t + 1)
    }
#undef STEP

    // ---- output heads: final h in buf0 cols (t=200 even), read fp16
    __syncthreads();
    for (int idx = tid; idx < CROWS * DD; idx += 128) {
        int rr = idx / DD, d = idx - rr * DD;
        const __half* hr = hsm + rr * HSTR;   // buf0 = cols 0-31
        float aL = b1[d], aA = b2[d];
#pragma unroll
        for (int u = 0; u < 32; ++u) {
            float hu = __half2float(hr[u]);
            aL = fmaf(hu, W1[u * DD + d], aL);
            aA = fmaf(hu, W2[u * DD + d], aA);
        }
        size_t grow = (size_t)blockIdx.x * CROWS + rr;
        out[grow * DD + d] = aL;
        out[(8192 + grow) * DD + d] = aA;
    }
}

extern "C" void kernel_launch(void* const* d_in, const int* in_sizes, int n_in,
                              void* d_out, int out_size) {
    const float* x  = (const float*)d_in[0];
    const float* W  = (const float*)d_in[1];
    const float* U  = (const float*)d_in[2];
    const float* b  = (const float*)d_in[3];
    const float* W1 = (const float*)d_in[4];
    const float* b1 = (const float*)d_in[5];
    const float* W2 = (const float*)d_in[6];
    const float* b2 = (const float*)d_in[7];
    float* out = (float*)d_out;

    // 8192 rows / 16 per CTA = 512 CTAs x 128 thr (4 warps, 2 pairs)
    lstm_r17_kernel<<<512, 128>>>(x, W, U, b, W1, b1, W2, b2, out);
}